// round 4
// baseline (speedup 1.0000x reference)
#include <cuda_runtime.h>
#include <cstdint>

#define BATCH   4
#define NF      16
#define NC      8
#define NPIX    262144            // 512*512
#define DELTA_V 0.5f
#define CMAX    100000.0f

#define CHUNKS   32
#define NBLOCKS  (CHUNKS * BATCH)   // 128 blocks <= 148 SMs -> all resident
#define NTHREADS 1024               // 32 warps/SM -> occ 50%
#define PAIRS_PER_CHUNK 4096        // (NPIX/2)/CHUNKS
#define PIXW     8                  // pixel-warps per block (256 pixel-threads)
#define P1_ITERS 16                 // 4096 / 256
#define PIX_PER_CHUNK 8192          // NPIX / CHUNKS
#define P2_QUADS 2                  // 8192 / (1024 threads * 4 px)

// ---- persistent scratch (device globals; rewritten every launch) ----
__device__ float g_part1 [BATCH][CHUNKS][NF][NC];
__device__ float g_part1c[BATCH][CHUNKS][NC];
__device__ float g_part2 [NBLOCKS];
__device__ unsigned g_bar_count = 0;
__device__ unsigned g_bar_gen   = 0;
__device__ unsigned g_fin_count = 0;

// ============================================================================
// Single fused kernel: pass1 sums -> grid barrier -> means -> pass2 -> final
// 1024 threads: warp w -> feature-group fg=w&3 (4 features), pixel-warp pw=w>>2
// ============================================================================
__global__ void __launch_bounds__(NTHREADS, 1)
fused_loss(const float* __restrict__ pred, const int* __restrict__ tgt,
           float* __restrict__ out)
{
    const int tid  = threadIdx.x;
    const int w    = tid >> 5;
    const int lane = tid & 31;
    const int fg   = w & 3;            // feature group (4 features)
    const int pw   = w >> 2;           // pixel-warp 0..7
    const int pl   = pw * 32 + lane;   // pixel-thread 0..255
    const int b     = blockIdx.x >> 5; // batch
    const int chunk = blockIdx.x & 31;

    const float* pb = pred + (size_t)b * NF * NPIX;
    const float* p0 = pb + (size_t)(fg * 4) * NPIX;
    const int*   t0 = tgt + (size_t)b * NPIX;

    __shared__ float s_s[4][PIXW][4][NC];   // [fg][pw][f][c]  4 KB
    __shared__ float s_c[PIXW][NC];
    __shared__ float s_cnt[NC];
    __shared__ float4 s_m4[4][NC];          // means: [fg][class] -> 4 features
    __shared__ float s_factor;
    __shared__ float s_red[32];
    __shared__ float s_f2[4];
    __shared__ unsigned s_last;

    // ---------------- Pass 1: masked per-class sums + counts ----------------
    {
        const int basePair = chunk * PAIRS_PER_CHUNK;
        float acc[4][NC];
        float cnt[NC];
#pragma unroll
        for (int f = 0; f < 4; f++)
#pragma unroll
            for (int c = 0; c < NC; c++) acc[f][c] = 0.f;
#pragma unroll
        for (int c = 0; c < NC; c++) cnt[c] = 0.f;

#pragma unroll 2
        for (int i = 0; i < P1_ITERS; i++) {
            const int n0 = (basePair + i * 256 + pl) * 2;
            const int2 g = *(const int2*)(t0 + n0);
            float2 v[4];
#pragma unroll
            for (int f = 0; f < 4; f++)
                v[f] = *(const float2*)(p0 + (size_t)f * NPIX + n0);

#pragma unroll
            for (int c = 0; c < NC; c++) {
                const float mx = (g.x == c) ? 1.0f : 0.0f;
                const float my = (g.y == c) ? 1.0f : 0.0f;
#pragma unroll
                for (int f = 0; f < 4; f++) {
                    acc[f][c] = fmaf(v[f].x, mx, acc[f][c]);
                    acc[f][c] = fmaf(v[f].y, my, acc[f][c]);
                }
                if (fg == 0) { cnt[c] += mx; cnt[c] += my; }
            }
        }

        // warp butterfly reductions (deterministic)
#pragma unroll
        for (int f = 0; f < 4; f++)
#pragma unroll
            for (int c = 0; c < NC; c++)
                for (int o = 16; o > 0; o >>= 1)
                    acc[f][c] += __shfl_xor_sync(0xffffffffu, acc[f][c], o);
        if (fg == 0) {
#pragma unroll
            for (int c = 0; c < NC; c++)
                for (int o = 16; o > 0; o >>= 1)
                    cnt[c] += __shfl_xor_sync(0xffffffffu, cnt[c], o);
        }

        if (lane == 0) {
#pragma unroll
            for (int f = 0; f < 4; f++)
#pragma unroll
                for (int c = 0; c < NC; c++)
                    s_s[fg][pw][f][c] = acc[f][c];
            if (fg == 0) {
#pragma unroll
                for (int c = 0; c < NC; c++)
                    s_c[pw][c] = cnt[c];
            }
        }
        __syncthreads();

        if (tid < 128) {
            const int fg2 = tid >> 5, f2 = (tid >> 3) & 3, c2 = tid & 7;
            float v = 0.f;
#pragma unroll
            for (int p = 0; p < PIXW; p++) v += s_s[fg2][p][f2][c2];
            __stcg(&g_part1[b][chunk][fg2 * 4 + f2][c2], v);
        }
        if (tid < NC) {
            float v = 0.f;
#pragma unroll
            for (int p = 0; p < PIXW; p++) v += s_c[p][tid];
            __stcg(&g_part1c[b][chunk][tid], v);
        }
    }

    // ---------------- Grid-wide barrier (generation sense) ------------------
    __syncthreads();
    if (tid == 0) {
        __threadfence();
        unsigned gen = *(volatile unsigned*)&g_bar_gen;
        if (atomicAdd(&g_bar_count, 1) == NBLOCKS - 1) {
            g_bar_count = 0;
            __threadfence();
            atomicAdd(&g_bar_gen, 1);
        } else {
            while (*(volatile unsigned*)&g_bar_gen == gen) { }
        }
        __threadfence();
    }
    __syncthreads();

    // ------------- Means (redundant per-block reduce over L2) ---------------
    if (tid < NC) {
        float s = 0.f;
#pragma unroll 8
        for (int x = 0; x < CHUNKS; x++) s += __ldcg(&g_part1c[b][x][tid]);
        s_cnt[tid] = s;
    }
    __syncthreads();
    if (tid < 128) {
        const int f = tid >> 3, c = tid & 7;
        float s = 0.f;
#pragma unroll 8
        for (int x = 0; x < CHUNKS; x++) s += __ldcg(&g_part1[b][x][f][c]);
        ((float*)&s_m4[f >> 2][c])[f & 3] = s / s_cnt[c];
    }
    if (tid == NTHREADS - 1) {
        float fs = 0.f;
#pragma unroll
        for (int c = 0; c < NC; c++) fs += 1.0f / s_cnt[c];
        s_factor = fs * (1.0f / NC);
    }
    __syncthreads();

    // ---------------- Pass 2: variance loss over same pixel range -----------
    float local = 0.f;
    const int pix0 = chunk * PIX_PER_CHUNK;
#pragma unroll
    for (int q = 0; q < P2_QUADS; q++) {
        const int n0 = pix0 + (q * NTHREADS + tid) * 4;
        const int4 g = *(const int4*)(t0 + n0);

        float sq0 = 0.f, sq1 = 0.f, sq2 = 0.f, sq3 = 0.f;
#pragma unroll
        for (int fg2 = 0; fg2 < 4; fg2++) {
            const float4 mx = s_m4[fg2][g.x];   // LDS.128, <=8 distinct addrs
            const float4 my = s_m4[fg2][g.y];
            const float4 mz = s_m4[fg2][g.z];
            const float4 mw = s_m4[fg2][g.w];
            const float* pf = pb + (size_t)(fg2 * 4) * NPIX + n0;
#pragma unroll
            for (int j = 0; j < 4; j++) {
                const float4 v = *(const float4*)(pf + (size_t)j * NPIX);
                float d;
                d = ((const float*)&mx)[j] - v.x; sq0 = fmaf(d, d, sq0);
                d = ((const float*)&my)[j] - v.y; sq1 = fmaf(d, d, sq1);
                d = ((const float*)&mz)[j] - v.z; sq2 = fmaf(d, d, sq2);
                d = ((const float*)&mw)[j] - v.w; sq3 = fmaf(d, d, sq3);
            }
        }
        float dd, tt;
        dd = sqrtf(sq0); tt = fminf(fmaxf(dd - DELTA_V, 0.f), CMAX); local = fmaf(tt, tt, local);
        dd = sqrtf(sq1); tt = fminf(fmaxf(dd - DELTA_V, 0.f), CMAX); local = fmaf(tt, tt, local);
        dd = sqrtf(sq2); tt = fminf(fmaxf(dd - DELTA_V, 0.f), CMAX); local = fmaf(tt, tt, local);
        dd = sqrtf(sq3); tt = fminf(fmaxf(dd - DELTA_V, 0.f), CMAX); local = fmaf(tt, tt, local);
    }

    // block reduce (fixed order)
    for (int o = 16; o > 0; o >>= 1)
        local += __shfl_xor_sync(0xffffffffu, local, o);
    if (lane == 0) s_red[w] = local;
    __syncthreads();
    if (tid < 32) {
        float v = s_red[tid];
        for (int o = 16; o > 0; o >>= 1)
            v += __shfl_xor_sync(0xffffffffu, v, o);
        if (tid == 0) __stcg(&g_part2[blockIdx.x], v * s_factor);
    }

    // ---------------- Final: last block reduces 128 partials -----------------
    __syncthreads();
    if (tid == 0) {
        __threadfence();
        s_last = (atomicAdd(&g_fin_count, 1) == NBLOCKS - 1) ? 1u : 0u;
    }
    __syncthreads();
    if (s_last) {
        if (tid < 128) {
            float v = __ldcg(&g_part2[tid]);
            for (int o = 16; o > 0; o >>= 1)
                v += __shfl_xor_sync(0xffffffffu, v, o);
            if (lane == 0) s_f2[w] = v;
        }
        __syncthreads();
        if (tid == 0) {
            out[0] = (s_f2[0] + s_f2[1]) + (s_f2[2] + s_f2[3]);
            g_fin_count = 0;   // reset for next graph replay
        }
    }
}

// ============================================================================
extern "C" void kernel_launch(void* const* d_in, const int* in_sizes, int n_in,
                              void* d_out, int out_size)
{
    const float* pred = (const float*)d_in[0];
    const int*   tgt  = (const int*)d_in[1];
    float* out = (float*)d_out;

    fused_loss<<<NBLOCKS, NTHREADS>>>(pred, tgt, out);
}

// round 5
// speedup vs baseline: 1.5377x; 1.5377x over previous
#include <cuda_runtime.h>
#include <cstdint>

#define BATCH   4
#define NF      16
#define NC      8
#define NPIX    262144            // 512*512
#define DELTA_V 0.5f
#define CMAX    100000.0f

// K1 config (proven R1): 64 chunks per batch, 256 threads (4 fg x 2 pw warps)
#define CHUNKS    64
#define K1_THREADS 256
#define PAIRS_PER_CHUNK 2048      // (NPIX/2)/CHUNKS
#define K1_ITERS  32              // PAIRS_PER_CHUNK / 64 pixel-threads

// K3 config: 64 blocks per batch, 512 threads, 4096 px/block
#define K3_BLOCKS  64
#define K3_THREADS 512
#define PIX_PER_K3BLK 4096
#define K3_ITERS   2              // 4096 / (512*4)

typedef unsigned long long u64;

// ---- scratch (device globals; fully rewritten every launch) ----
__device__ float g_part1 [BATCH][CHUNKS][NF][NC];
__device__ float g_part1c[BATCH][CHUNKS][NC];
__device__ float g_part2 [BATCH * K3_BLOCKS];
__device__ unsigned g_fin_count = 0;

// ---- packed f32x2 helpers (Blackwell) ----
__device__ __forceinline__ u64 pack2(float lo, float hi) {
    u64 r; asm("mov.b64 %0, {%1, %2};" : "=l"(r) : "f"(lo), "f"(hi)); return r;
}
__device__ __forceinline__ void unpack2(u64 v, float& lo, float& hi) {
    asm("mov.b64 {%0, %1}, %2;" : "=f"(lo), "=f"(hi) : "l"(v));
}
__device__ __forceinline__ u64 fma2(u64 a, u64 b, u64 c) {
    u64 d; asm("fma.rn.f32x2 %0, %1, %2, %3;" : "=l"(d) : "l"(a), "l"(b), "l"(c)); return d;
}
__device__ __forceinline__ u64 add2(u64 a, u64 b) {
    u64 d; asm("add.rn.f32x2 %0, %1, %2;" : "=l"(d) : "l"(a), "l"(b)); return d;
}

// ============================================================================
// K1: masked per-class sums + counts (packed f32x2). Proven R1 kernel.
// ============================================================================
__global__ void __launch_bounds__(K1_THREADS)
k1_sums(const float* __restrict__ pred, const int* __restrict__ tgt)
{
    const int tid  = threadIdx.x;
    const int w    = tid >> 5;
    const int lane = tid & 31;
    const int fg   = w & 3;
    const int pw   = w >> 2;
    const int pl   = pw * 32 + lane;          // pixel-thread 0..63
    const int b    = blockIdx.y;

    const float* p0 = pred + (size_t)(b * NF + fg * 4) * NPIX;
    const int*   t0 = tgt  + (size_t)b * NPIX;
    const int basePair = blockIdx.x * PAIRS_PER_CHUNK;

    u64 acc[4][NC];
    u64 cnt[NC];
#pragma unroll
    for (int f = 0; f < 4; f++)
#pragma unroll
        for (int c = 0; c < NC; c++) acc[f][c] = 0ULL;
#pragma unroll
    for (int c = 0; c < NC; c++) cnt[c] = 0ULL;

    for (int i = 0; i < K1_ITERS; i++) {
        const int pair = basePair + i * 64 + pl;
        const int n0   = pair * 2;
        const int2 g   = *(const int2*)(t0 + n0);

        u64 m[NC];
#pragma unroll
        for (int c = 0; c < NC; c++)
            m[c] = pack2(g.x == c ? 1.0f : 0.0f, g.y == c ? 1.0f : 0.0f);

#pragma unroll
        for (int f = 0; f < 4; f++) {
            const u64 v = *(const u64*)(p0 + (size_t)f * NPIX + n0);
#pragma unroll
            for (int c = 0; c < NC; c++)
                acc[f][c] = fma2(v, m[c], acc[f][c]);
        }
        if (fg == 0) {
#pragma unroll
            for (int c = 0; c < NC; c++) cnt[c] = add2(cnt[c], m[c]);
        }
    }

    // warp butterfly reduction (deterministic)
#pragma unroll
    for (int f = 0; f < 4; f++)
#pragma unroll
        for (int c = 0; c < NC; c++)
            for (int o = 16; o > 0; o >>= 1)
                acc[f][c] = add2(acc[f][c], __shfl_xor_sync(0xffffffffu, acc[f][c], o));
    if (fg == 0) {
#pragma unroll
        for (int c = 0; c < NC; c++)
            for (int o = 16; o > 0; o >>= 1)
                cnt[c] = add2(cnt[c], __shfl_xor_sync(0xffffffffu, cnt[c], o));
    }

    __shared__ float s_s[4][2][4][NC];
    __shared__ float s_c[2][NC];
    if (lane == 0) {
#pragma unroll
        for (int f = 0; f < 4; f++)
#pragma unroll
            for (int c = 0; c < NC; c++) {
                float lo, hi; unpack2(acc[f][c], lo, hi);
                s_s[fg][pw][f][c] = lo + hi;
            }
        if (fg == 0) {
#pragma unroll
            for (int c = 0; c < NC; c++) {
                float lo, hi; unpack2(cnt[c], lo, hi);
                s_c[pw][c] = lo + hi;
            }
        }
    }
    __syncthreads();

    if (tid < 128) {
        const int fg2 = tid >> 5, f2 = (tid >> 3) & 3, c2 = tid & 7;
        __stcg(&g_part1[b][blockIdx.x][fg2 * 4 + f2][c2],
               s_s[fg2][0][f2][c2] + s_s[fg2][1][f2][c2]);
    }
    if (tid < NC)
        __stcg(&g_part1c[b][blockIdx.x][tid], s_c[0][tid] + s_c[1][tid]);
}

// ============================================================================
// K3': means (redundant per block) -> variance loss -> last-block final
// ============================================================================
__global__ void __launch_bounds__(K3_THREADS)
k3_dist(const float* __restrict__ pred, const int* __restrict__ tgt,
        float* __restrict__ out)
{
    const int tid  = threadIdx.x;
    const int w    = tid >> 5;
    const int lane = tid & 31;
    const int b    = blockIdx.y;
    const int blk  = blockIdx.x;

    __shared__ float  s_tmp[128][4];
    __shared__ float  s_ctmp[NC][4];
    __shared__ float  s_cnt[NC];
    __shared__ float4 s_m4[4][NC];       // [feature-group][class] -> 4 features
    __shared__ float  s_factor;
    __shared__ float  s_red[16];
    __shared__ float  s_f2[8];
    __shared__ unsigned s_last;

    // ---- counts: 32 threads, 4-way split over chunks ----
    if (tid < 32) {
        const int c = tid >> 2, part = tid & 3;
        float s = 0.f;
#pragma unroll
        for (int i = 0; i < CHUNKS / 4; i++)
            s += __ldcg(&g_part1c[b][part * (CHUNKS / 4) + i][c]);
        s_ctmp[c][part] = s;
    }
    // ---- feature-class sums: 512 threads, 4-way split ----
    {
        const int idx = tid >> 2, part = tid & 3;   // idx = f*8+c
        const int f = idx >> 3, c = idx & 7;
        float s = 0.f;
#pragma unroll
        for (int i = 0; i < CHUNKS / 4; i++)
            s += __ldcg(&g_part1[b][part * (CHUNKS / 4) + i][f][c]);
        s_tmp[idx][part] = s;
    }
    __syncthreads();
    if (tid < NC)
        s_cnt[tid] = (s_ctmp[tid][0] + s_ctmp[tid][1])
                   + (s_ctmp[tid][2] + s_ctmp[tid][3]);
    __syncthreads();
    if (tid < 128) {
        const int f = tid >> 3, c = tid & 7;
        const float s = (s_tmp[tid][0] + s_tmp[tid][1])
                      + (s_tmp[tid][2] + s_tmp[tid][3]);
        ((float*)&s_m4[f >> 2][c])[f & 3] = s / s_cnt[c];
    }
    if (tid == K3_THREADS - 1) {
        float fs = 0.f;
#pragma unroll
        for (int c = 0; c < NC; c++) fs += 1.0f / s_cnt[c];
        s_factor = fs * (1.0f / NC);
    }
    __syncthreads();

    // ---- pass 2: per-pixel variance loss ----
    const float* pb = pred + (size_t)b * NF * NPIX;
    const int*   t0 = tgt  + (size_t)b * NPIX;
    const int pix0 = blk * PIX_PER_K3BLK;

    float local = 0.f;
#pragma unroll
    for (int q = 0; q < K3_ITERS; q++) {
        const int n0 = pix0 + (q * K3_THREADS + tid) * 4;
        const int4 g = *(const int4*)(t0 + n0);

        float sq0 = 0.f, sq1 = 0.f, sq2 = 0.f, sq3 = 0.f;
#pragma unroll
        for (int fg = 0; fg < 4; fg++) {
            const float4 mx = s_m4[fg][g.x];   // LDS.128, <=8 distinct addrs
            const float4 my = s_m4[fg][g.y];   //   -> conflict-free multicast
            const float4 mz = s_m4[fg][g.z];
            const float4 mw = s_m4[fg][g.w];
            const float* pf = pb + (size_t)(fg * 4) * NPIX + n0;
#pragma unroll
            for (int j = 0; j < 4; j++) {
                const float4 v = *(const float4*)(pf + (size_t)j * NPIX);
                float d;
                d = ((const float*)&mx)[j] - v.x; sq0 = fmaf(d, d, sq0);
                d = ((const float*)&my)[j] - v.y; sq1 = fmaf(d, d, sq1);
                d = ((const float*)&mz)[j] - v.z; sq2 = fmaf(d, d, sq2);
                d = ((const float*)&mw)[j] - v.w; sq3 = fmaf(d, d, sq3);
            }
        }
        float dd, tt;
        dd = sqrtf(sq0); tt = fminf(fmaxf(dd - DELTA_V, 0.f), CMAX); local = fmaf(tt, tt, local);
        dd = sqrtf(sq1); tt = fminf(fmaxf(dd - DELTA_V, 0.f), CMAX); local = fmaf(tt, tt, local);
        dd = sqrtf(sq2); tt = fminf(fmaxf(dd - DELTA_V, 0.f), CMAX); local = fmaf(tt, tt, local);
        dd = sqrtf(sq3); tt = fminf(fmaxf(dd - DELTA_V, 0.f), CMAX); local = fmaf(tt, tt, local);
    }

    // block reduce (fixed order)
    for (int o = 16; o > 0; o >>= 1)
        local += __shfl_xor_sync(0xffffffffu, local, o);
    if (lane == 0) s_red[w] = local;
    __syncthreads();
    if (tid < 32) {
        float v = (tid < 16) ? s_red[tid] : 0.f;
        for (int o = 16; o > 0; o >>= 1)
            v += __shfl_xor_sync(0xffffffffu, v, o);
        if (tid == 0) __stcg(&g_part2[b * K3_BLOCKS + blk], v * s_factor);
    }

    // ---- last-block final reduction of 256 partials ----
    __syncthreads();
    if (tid == 0) {
        __threadfence();
        s_last = (atomicAdd(&g_fin_count, 1) == (BATCH * K3_BLOCKS) - 1) ? 1u : 0u;
    }
    __syncthreads();
    if (s_last) {
        if (tid < 256) {
            float v = __ldcg(&g_part2[tid]);
            for (int o = 16; o > 0; o >>= 1)
                v += __shfl_xor_sync(0xffffffffu, v, o);
            if (lane == 0) s_f2[w] = v;
        }
        __syncthreads();
        if (tid == 0) {
            out[0] = ((s_f2[0] + s_f2[1]) + (s_f2[2] + s_f2[3]))
                   + ((s_f2[4] + s_f2[5]) + (s_f2[6] + s_f2[7]));
            g_fin_count = 0;   // reset for next graph replay
        }
    }
}

// ============================================================================
extern "C" void kernel_launch(void* const* d_in, const int* in_sizes, int n_in,
                              void* d_out, int out_size)
{
    const float* pred = (const float*)d_in[0];
    const int*   tgt  = (const int*)d_in[1];
    float* out = (float*)d_out;

    k1_sums<<<dim3(CHUNKS, BATCH), K1_THREADS>>>(pred, tgt);
    k3_dist<<<dim3(K3_BLOCKS, BATCH), K3_THREADS>>>(pred, tgt, out);
}